// round 17
// baseline (speedup 1.0000x reference)
#include <cuda_runtime.h>
#include <cuda_fp16.h>
#include <cstdint>

// BinaryConv2d via Winograd F(2x2,3x3) + mma.sync HMMA.
// R17: intra-iter fragment double-buffering in GEMM; fused pad+winograd_x; float4 inverse.

#define NB 32
#define CI 128
#define CO 256
#define HH 56
#define HP 58
#define PIXN (HH*HH)
#define TPI  784              // 28*28 tiles per image
#define NTILE (NB*TPI)        // 25088
#define NBLK  196             // NTILE/128
#define XNPER 8
#define NITER (2*XNPER)       // 16 k-chunks per CTA
#define STAGES 4

// Winograd input, chunked+swizzled: [(xn*392 + blk*2 + sub)][pix(128)][64 halfs swz]
__device__ __align__(256) __half g_u2[(size_t)16*NBLK*2*128*64];
// Winograd weights, chunked+swizzled: [(xn*2+sub)][oc(256)][64 halfs swz]
__device__ __align__(256) __half g_v2[(size_t)16*2*256*64];
// GEMM result M[xn][tile][oc]
__device__ __align__(16) __half g_m[(size_t)16*NTILE*CO];

// ---------------- fused pad + fp16 + input Winograd transform ----------------
// block = (n, ti): 4 padded rows x 58 wp x 128 c in smem (fp16), 28 tj tiles out.
#define XW 136                        // padded c-stride (halves) to dodge bank conflicts
__global__ __launch_bounds__(256)
void winograd_x_fused(const float* __restrict__ x) {
    __shared__ __half s[4 * 58 * XW];
    const int ti = blockIdx.x % 28;
    const int n  = blockIdx.x / 28;
    const int tid = threadIdx.x;

    // zero smem
    for (int i = tid; i < 4 * 58 * XW / 2; i += 256)
        ((uint32_t*)s)[i] = 0;
    __syncthreads();

    // load 4 rows (hin = 2ti-1+r), fp16-quantize, wp = win+1
#pragma unroll
    for (int r = 0; r < 4; r++) {
        const int hin = 2 * ti - 1 + r;
        if ((unsigned)hin < HH) {
            const float* src = x + ((size_t)n * CI * HH + hin) * HH;
            for (int idx = tid; idx < CI * HH; idx += 256) {
                int c = idx / HH, w = idx - (idx / HH) * HH;
                s[(r * 58 + w + 1) * XW + c] = __float2half_rn(src[(size_t)c * PIXN + w]);
            }
        }
    }
    __syncthreads();

    // compute 28 tj x 64 c-pairs
    for (int u = tid; u < 28 * 64; u += 256) {
        const int c2 = u & 63;
        const int tj = u >> 6;
        const int c  = 2 * c2;

        float d0[4][4], d1[4][4];
#pragma unroll
        for (int i = 0; i < 4; i++)
#pragma unroll
            for (int ss = 0; ss < 4; ss++) {
                __half2 hv = *(__half2*)&s[(i * 58 + 2 * tj + ss) * XW + c];
                d0[i][ss] = __low2float(hv);
                d1[i][ss] = __high2float(hv);
            }

        float t0[4][4], t1[4][4];
#pragma unroll
        for (int ss = 0; ss < 4; ss++) {
            t0[0][ss] = d0[0][ss] - d0[2][ss];  t1[0][ss] = d1[0][ss] - d1[2][ss];
            t0[1][ss] = d0[1][ss] + d0[2][ss];  t1[1][ss] = d1[1][ss] + d1[2][ss];
            t0[2][ss] = d0[2][ss] - d0[1][ss];  t1[2][ss] = d1[2][ss] - d1[1][ss];
            t0[3][ss] = d0[1][ss] - d0[3][ss];  t1[3][ss] = d1[1][ss] - d1[3][ss];
        }
        float u0[4][4], u1[4][4];
#pragma unroll
        for (int i = 0; i < 4; i++) {
            u0[i][0] = t0[i][0] - t0[i][2];  u1[i][0] = t1[i][0] - t1[i][2];
            u0[i][1] = t0[i][1] + t0[i][2];  u1[i][1] = t1[i][1] + t1[i][2];
            u0[i][2] = t0[i][2] - t0[i][1];  u1[i][2] = t1[i][2] - t1[i][1];
            u0[i][3] = t0[i][1] - t0[i][3];  u1[i][3] = t1[i][1] - t1[i][3];
        }

        const int t   = n * TPI + ti * 28 + tj;
        const int blk = t >> 7;
        const int pix = t & 127;
        const int sub = c >> 6;
        const int e   = c & 7;
        const int uw  = ((c >> 3) & 7) ^ (pix & 7);
        const size_t inner = ((size_t)pix * 64) + uw * 8 + e;
#pragma unroll
        for (int xi = 0; xi < 4; xi++)
#pragma unroll
            for (int nu = 0; nu < 4; nu++) {
                int xn = xi * 4 + nu;
                *(__half2*)&g_u2[((size_t)xn * (NBLK * 2) + blk * 2 + sub) * 8192 + inner] =
                    __floats2half2_rn(u0[xi][nu], u1[xi][nu]);
            }
    }
}

// ---------------- weight Winograd transform (swizzled chunk layout) ----------------
__global__ __launch_bounds__(256)
void winograd_w_kernel(const float* __restrict__ w) {
    int idx = blockIdx.x * 256 + threadIdx.x;    // over CO*CI
    if (idx >= CO * CI) return;
    int oc = idx >> 7;
    int c  = idx & 127;
    float g[3][3];
#pragma unroll
    for (int r = 0; r < 3; r++)
#pragma unroll
        for (int s = 0; s < 3; s++)
            g[r][s] = (w[((size_t)(oc * CI + c)) * 9 + r * 3 + s] >= 0.0f) ? 1.0f : -1.0f;
    float gg[4][3];
#pragma unroll
    for (int s = 0; s < 3; s++) {
        gg[0][s] = g[0][s];
        gg[1][s] = 0.5f * (g[0][s] + g[1][s] + g[2][s]);
        gg[2][s] = 0.5f * (g[0][s] - g[1][s] + g[2][s]);
        gg[3][s] = g[2][s];
    }
    const int sub = c >> 6;
    const int e   = c & 7;
    const int uw  = ((c >> 3) & 7) ^ (oc & 7);
    const size_t inner = ((size_t)oc * 64) + uw * 8 + e;
#pragma unroll
    for (int i = 0; i < 4; i++) {
        float v[4];
        v[0] = gg[i][0];
        v[1] = 0.5f * (gg[i][0] + gg[i][1] + gg[i][2]);
        v[2] = 0.5f * (gg[i][0] - gg[i][1] + gg[i][2]);
        v[3] = gg[i][2];
#pragma unroll
        for (int nu = 0; nu < 4; nu++) {
            int xn = i * 4 + nu;
            g_v2[((size_t)xn * 2 + sub) * 16384 + inner] = __float2half_rn(v[nu]);
        }
    }
}

// ---------------- GEMM kernel ----------------
__device__ __forceinline__ uint32_t smem_u32(const void* p) {
    uint32_t a;
    asm("{ .reg .u64 t; cvta.to.shared.u64 t, %1; cvt.u32.u64 %0, t; }" : "=r"(a) : "l"(p));
    return a;
}
__device__ __forceinline__ void bulk_cp(uint32_t dst, const void* src, uint32_t bytes, uint32_t mbar) {
    asm volatile("cp.async.bulk.shared::cta.global.mbarrier::complete_tx::bytes [%0], [%1], %2, [%3];"
        :: "r"(dst), "l"(src), "r"(bytes), "r"(mbar) : "memory");
}
#define MBAR_INIT(a, c) asm volatile("mbarrier.init.shared.b64 [%0], %1;" :: "r"(a), "r"(c) : "memory")
#define MBAR_EXPECT(a, b) asm volatile("mbarrier.arrive.expect_tx.shared.b64 _, [%0], %1;" :: "r"(a), "r"(b) : "memory")
#define FENCE_ASYNC() asm volatile("fence.proxy.async.shared::cta;" ::: "memory")
#define MBAR_WAIT(a, ph) do { \
    uint32_t _m = (a); uint32_t _p = (ph); uint32_t _d; \
    asm volatile("{\n\t.reg .pred p;\n\tmbarrier.try_wait.parity.acquire.cta.shared::cta.b64 p, [%1], %2;\n\tselp.b32 %0,1,0,p;\n\t}" \
        : "=r"(_d) : "r"(_m), "r"(_p) : "memory"); \
    if (!_d) { \
        asm volatile("{\n\t.reg .pred P1;\nWL_%=:\n\tmbarrier.try_wait.parity.acquire.cta.shared::cta.b64 P1, [%0], %1, 0x989680;\n\t@P1 bra.uni WD_%=;\n\tbra.uni WL_%=;\nWD_%=:\n\t}" \
            :: "r"(_m), "r"(_p) : "memory"); \
    } } while (0)

__device__ __forceinline__ void ldsm4(uint32_t* r, uint32_t addr) {
    asm volatile("ldmatrix.sync.aligned.m8n8.x4.shared.b16 {%0,%1,%2,%3}, [%4];"
        : "=r"(r[0]), "=r"(r[1]), "=r"(r[2]), "=r"(r[3]) : "r"(addr));
}
__device__ __forceinline__ void mma16816(float* c, const uint32_t* a, uint32_t b0, uint32_t b1) {
    asm volatile("mma.sync.aligned.m16n8k16.row.col.f32.f16.f16.f32 "
        "{%0,%1,%2,%3}, {%4,%5,%6,%7}, {%8,%9}, {%0,%1,%2,%3};"
        : "+f"(c[0]), "+f"(c[1]), "+f"(c[2]), "+f"(c[3])
        : "r"(a[0]), "r"(a[1]), "r"(a[2]), "r"(a[3]), "r"(b0), "r"(b1));
}

#define A_ST  16384                  // 128 pix x 64 k x fp16 (swizzled rows)
#define B_ST  32768                  // 256 oc  x 64 k x fp16 (swizzled rows)
#define ST_BYTES (A_ST + B_ST)       // 48 KB / stage
#define SMEM_SZ (STAGES * ST_BYTES)  // 192 KB

__global__ __launch_bounds__(256, 1)
void binconv_wino_gemm(void) {
    extern __shared__ char smem[];
    __shared__ __align__(8) uint64_t mbar[STAGES];
    const uint32_t sb = smem_u32(smem);
    const uint32_t mb = smem_u32(&mbar[0]);

    const int tid  = threadIdx.x;
    const int wid  = tid >> 5;
    const int lane = tid & 31;
    const int blk  = blockIdx.x;
    const int t0   = blk * 128;
    const int xn0  = blockIdx.y * XNPER;

    if (tid == 0) {
#pragma unroll
        for (int s = 0; s < STAGES; s++) MBAR_INIT(mb + s * 8, 1);
    }
    __syncthreads();

    auto issue = [&](int kk) {
        if (kk < NITER) {
            const int s   = kk % STAGES;
            const int xl  = kk >> 1;
            const int sub = kk & 1;
            const uint32_t soff = (uint32_t)s * ST_BYTES;
            MBAR_EXPECT(mb + s * 8, (uint32_t)ST_BYTES);
            bulk_cp(sb + soff,
                    g_u2 + ((size_t)(xn0 + xl) * (NBLK * 2) + blk * 2 + sub) * 8192,
                    A_ST, mb + s * 8);
            bulk_cp(sb + A_ST + soff,
                    g_v2 + ((size_t)(xn0 + xl) * 2 + sub) * 16384,
                    B_ST, mb + s * 8);
        }
    };

    if (tid == 0) { FENCE_ASYNC(); issue(0); issue(1); issue(2); }

    // warp tiling: 2 (M) x 4 (N); warp tile 64 x 64
    const int wm = (wid & 1) * 64;
    const int wn = (wid >> 1) * 64;

    float acc[4][8][4];
#pragma unroll
    for (int mi = 0; mi < 4; mi++)
#pragma unroll
        for (int nb = 0; nb < 8; nb++)
#pragma unroll
            for (int j = 0; j < 4; j++) acc[mi][nb][j] = 0.0f;

    // ldmatrix lane addressing (swizzled row layout: addr = row*128 + (unit ^ (row&7))*16)
    const int prow = wm + (lane & 15);
    const int ak   = lane >> 4;
    const int brow = wn + (lane & 7) + ((lane >> 4) << 3);
    const int bk   = (lane >> 3) & 1;
    const int qr   = lane >> 2;
    const int oc2  = (lane & 3) * 2;

    for (int kk = 0; kk < NITER; kk++) {
        const int s = kk % STAGES;
        const uint32_t soff = (uint32_t)s * ST_BYTES;
        MBAR_WAIT(mb + s * 8, (kk / STAGES) & 1);
        __syncthreads();
        if (tid == 0) { FENCE_ASYNC(); issue(kk + 3); }

        // intra-iter double-buffered fragments: preload kb=0, overlap kb+1 loads with kb MMAs
        uint32_t af[2][4][4], bf[2][4][4];
        {
            const uint32_t sa  = (uint32_t)((ak ^ (prow & 7)) << 4);
            const uint32_t sbz = (uint32_t)((bk ^ (brow & 7)) << 4);
#pragma unroll
            for (int mi = 0; mi < 4; mi++)
                ldsm4(af[0][mi], sb + soff + (uint32_t)(prow + mi * 16) * 128 + sa);
#pragma unroll
            for (int nj = 0; nj < 4; nj++)
                ldsm4(bf[0][nj], sb + A_ST + soff + (uint32_t)(brow + nj * 16) * 128 + sbz);
        }
#pragma unroll
        for (int kb = 0; kb < 4; kb++) {
            const int cur = kb & 1, nxt = cur ^ 1;
            if (kb < 3) {
                const uint32_t sa  = (uint32_t)(((2 * (kb + 1) + ak) ^ (prow & 7)) << 4);
                const uint32_t sbz = (uint32_t)(((2 * (kb + 1) + bk) ^ (brow & 7)) << 4);
#pragma unroll
                for (int mi = 0; mi < 4; mi++)
                    ldsm4(af[nxt][mi], sb + soff + (uint32_t)(prow + mi * 16) * 128 + sa);
#pragma unroll
                for (int nj = 0; nj < 4; nj++)
                    ldsm4(bf[nxt][nj], sb + A_ST + soff + (uint32_t)(brow + nj * 16) * 128 + sbz);
            }
#pragma unroll
            for (int mi = 0; mi < 4; mi++)
#pragma unroll
                for (int nb = 0; nb < 8; nb++) {
                    const uint32_t* bp = bf[cur][nb >> 1];
                    if (nb & 1) mma16816(acc[mi][nb], af[cur][mi], bp[2], bp[3]);
                    else        mma16816(acc[mi][nb], af[cur][mi], bp[0], bp[1]);
                }
        }

        if (kk & 1) {
            // finished xn = xn0 + (kk>>1): store M (fp16), reset acc
            const int xn = xn0 + (kk >> 1);
#pragma unroll
            for (int mi = 0; mi < 4; mi++) {
#pragma unroll
                for (int half = 0; half < 2; half++) {
                    const int row = wm + mi * 16 + half * 8 + qr;
                    __half2* mp = (__half2*)(g_m + ((size_t)xn * NTILE + t0 + row) * 256);
#pragma unroll
                    for (int nb = 0; nb < 8; nb++) {
                        const int oc = wn + nb * 8 + oc2;
                        mp[oc >> 1] = __floats2half2_rn(acc[mi][nb][half * 2 + 0],
                                                        acc[mi][nb][half * 2 + 1]);
                        acc[mi][nb][half * 2 + 0] = 0.0f;
                        acc[mi][nb][half * 2 + 1] = 0.0f;
                    }
                }
            }
        }
    }
}

// ---------------- inverse transform kernel ----------------
#define SMB 140                       // bytes per (xn,tj) smem row (70 halfs, odd stride)
#define INV_SMEM (16*28*SMB)          // 62720 B

__global__ __launch_bounds__(512)
void binconv_wino_inverse(const float* __restrict__ bias, float* __restrict__ out) {
    extern __shared__ char sm[];
    const int tid = threadIdx.x;
    const int bi  = blockIdx.x;           // n*28 + ti
    const int n   = bi / 28;
    const int ti  = bi - n * 28;
    const int ocb = blockIdx.y * 64;
    const int tbase = n * TPI + ti * 28;

    for (int u = tid; u < 16 * 28 * 8; u += 512) {
        int xn = u / 224;
        int r  = u - xn * 224;
        int tj = r >> 3;
        int sg = r & 7;
        const uint4 v = *(const uint4*)(g_m + ((size_t)xn * NTILE + tbase + tj) * 256 + ocb + sg * 8);
        char* d = sm + (xn * 28 + tj) * SMB + sg * 16;
        ((uint32_t*)d)[0] = v.x;
        ((uint32_t*)d)[1] = v.y;
        ((uint32_t*)d)[2] = v.z;
        ((uint32_t*)d)[3] = v.w;
    }
    __syncthreads();

    // 14 tj-pairs x 32 oc-pairs = 448 units; float4 output stores
    if (tid < 448) {
        const int tj2 = tid % 14;
        const int o2  = tid / 14;
        float m[16][2][2];                 // [xn][tjj][lane(l)]
#pragma unroll
        for (int xn = 0; xn < 16; xn++)
#pragma unroll
            for (int tjj = 0; tjj < 2; tjj++) {
                __half2 hv = *(__half2*)(sm + (xn * 28 + 2 * tj2 + tjj) * SMB + o2 * 4);
                m[xn][tjj][0] = __low2float(hv);
                m[xn][tjj][1] = __high2float(hv);
            }
#pragma unroll
        for (int l = 0; l < 2; l++) {
            const int oc = ocb + o2 * 2 + l;
            const float b = __ldg(&bias[oc]);
            float y[2][4];                 // [i][4 cols]
#pragma unroll
            for (int tjj = 0; tjj < 2; tjj++) {
                float r0[4], r1[4];
#pragma unroll
                for (int nu = 0; nu < 4; nu++) {
                    r0[nu] = m[0 * 4 + nu][tjj][l] + m[1 * 4 + nu][tjj][l] + m[2 * 4 + nu][tjj][l];
                    r1[nu] = m[1 * 4 + nu][tjj][l] - m[2 * 4 + nu][tjj][l] - m[3 * 4 + nu][tjj][l];
                }
                y[0][tjj * 2 + 0] = r0[0] + r0[1] + r0[2] + b;
                y[0][tjj * 2 + 1] = r0[1] - r0[2] - r0[3] + b;
                y[1][tjj * 2 + 0] = r1[0] + r1[1] + r1[2] + b;
                y[1][tjj * 2 + 1] = r1[1] - r1[2] - r1[3] + b;
            }
            float* ob = out + ((size_t)n * CO + oc) * PIXN + (size_t)(2 * ti) * HH + 4 * tj2;
            *(float4*)ob        = *(float4*)y[0];
            *(float4*)(ob + HH) = *(float4*)y[1];
        }
    }
}

// ---------------- launch ----------------
extern "C" void kernel_launch(void* const* d_in, const int* in_sizes, int n_in,
                              void* d_out, int out_size) {
    const float* x      = (const float*)d_in[0];
    const float* weight = (const float*)d_in[1];
    const float* bias   = (const float*)d_in[2];
    float* out          = (float*)d_out;

    cudaFuncSetAttribute(binconv_wino_gemm,
                         cudaFuncAttributeMaxDynamicSharedMemorySize, SMEM_SZ);
    cudaFuncSetAttribute(binconv_wino_inverse,
                         cudaFuncAttributeMaxDynamicSharedMemorySize, INV_SMEM);

    winograd_x_fused<<<NB * 28, 256>>>(x);
    winograd_w_kernel<<<(CO * CI + 255) / 256, 256>>>(weight);

    dim3 ggrid(NBLK, 16 / XNPER);
    binconv_wino_gemm<<<ggrid, 256, SMEM_SZ>>>();

    dim3 igrid(NB * 28, CO / 64);
    binconv_wino_inverse<<<igrid, 512, INV_SMEM>>>(bias, out);
}